// round 10
// baseline (speedup 1.0000x reference)
#include <cuda_runtime.h>

#define FULLM 0xFFFFFFFFu

// ---------------- scratch (device globals; no allocations allowed) ----------
static __device__ float g_Lo[64*128*8];
static __device__ float g_Ro[64*128*8];
static __device__ float g_he[16384*128];  // unmixed per-expert h: [grow][e*16+j]
static __device__ float g_hL[8192*16];
static __device__ float g_hR[8192*16];
static __device__ float g_part[128*16*2]; // per-mix-block {sum,sumsq} per column
static __device__ float g_mxw[8192*48];   // xW for mid-GRU layer0 (incl. bias)
static __device__ float g_zlast[64*16];
static __device__ float g_hdec[64*16];

// fast activations (scan kernels only; MUFU.TANH, max abs err ~5e-4)
__device__ __forceinline__ float tanh_f(float x){
  float y;
  asm("tanh.approx.f32 %0, %1;" : "=f"(y) : "f"(x));
  return y;
}
__device__ __forceinline__ float sigm(float x){
  return 0.5f*tanh_f(0.5f*x) + 0.5f;
}
#define BARRIER_64() asm volatile("bar.sync 1, 64;" ::: "memory")

// ---------------- fat kernel: gate GRU (blocks 0..127) + ae GEMM (128..383) --
// gate: warp 0 = GRU layer0, warp 1 = GRU layer1 one 8-step chunk behind;
//       h0 handed to warp1 via double-buffered smem chunk ring + bar.sync.
//       Intra-warp h broadcast is register+shfl (no syncwarp, no readback).
// gemm: 64 rows/block, w1 (64KB) + x (32KB) staged in dynamic smem; writes
//       UNMIXED per-expert h (+b1) to g_he — no dependency on gate output.
__global__ __launch_bounds__(256) void fat_kernel(
    const float* __restrict__ Local, const float* __restrict__ Remote,
    const float* __restrict__ Wih0, const float* __restrict__ Whh0,
    const float* __restrict__ bih0, const float* __restrict__ bhh0,
    const float* __restrict__ Wih1, const float* __restrict__ Whh1,
    const float* __restrict__ bih1, const float* __restrict__ bhh1,
    const float* __restrict__ w1, const float* __restrict__ b1)
{
  extern __shared__ float sm[];
  int blk = blockIdx.x;
  int tid = threadIdx.x;

  if (blk < 128){
    // ---------------- gate GRU path ----------------
    float* xw0  = sm;                                  // 128*24
    float* hist = sm + 3072;                           // 128*8
    float (*h0c)[8][8] = (float(*)[8][8])(sm + 4096);  // chunk ring (16B-aligned)
    const float* __restrict__ seq = ((blk < 64) ? Local : Remote) + (size_t)(blk & 63)*(128*132);
    float* outp = ((blk < 64) ? g_Lo : g_Ro) + (size_t)(blk & 63)*(128*8);

    // all 256 threads precompute xW for layer0 (features at [...,128..130])
    for (int idx = tid; idx < 128*24; idx += 256){
      int t = idx / 24, j = idx - t*24;
      const float* xp = seq + t*132 + 128;
      xw0[idx] = bih0[j] + Wih0[j*3+0]*xp[0] + Wih0[j*3+1]*xp[1] + Wih0[j*3+2]*xp[2];
    }
    __syncthreads();
    if (tid >= 64) return;

    int warp = tid >> 5, lane = tid & 31;
    int j = (lane < 24) ? lane : 0;
    int jr = lane & 7;

    if (warp == 0){
      // -------- producer: layer0 (h0 in regs, shfl broadcast) --------
      float w0[8];
      #pragma unroll
      for (int i=0;i<8;i++) w0[i]=Whh0[j*8+i];
      float b0 = bhh0[j];
      float h0 = 0.f;
      for (int c=0;c<17;c++){
        if (c<16){
          #pragma unroll
          for (int s8=0;s8<8;s8++){
            int t = c*8 + s8;
            float s;
            if (t == 0){ s = b0; }
            else {
              float p0=0.f, p1=0.f;
              #pragma unroll
              for (int i=0;i<4;i++) p0 += w0[i]*__shfl_sync(FULLM, h0, i);
              #pragma unroll
              for (int i=4;i<8;i++) p1 += w0[i]*__shfl_sync(FULLM, h0, i);
              s = b0 + p0 + p1;
            }
            float sr = __shfl_sync(FULLM, s, jr);
            float sz = __shfl_sync(FULLM, s, 8+jr);
            float sn = __shfl_sync(FULLM, s, 16+jr);
            float r = sigm(xw0[t*24 + jr]      + sr);
            float z = sigm(xw0[t*24 + 8 + jr]  + sz);
            float n = tanh_f(xw0[t*24 + 16 + jr] + r*sn);
            h0 = (1.f - z)*n + z*h0;
            if (lane < 8) h0c[(t>>3)&1][t&7][lane] = h0;
          }
        }
        BARRIER_64();
      }
    } else {
      // -------- consumer: layer1 (one chunk behind; h1 in regs via shfl) ----
      float wi[8], wh[8];
      #pragma unroll
      for (int i=0;i<8;i++){ wi[i]=Wih1[j*8+i]; wh[i]=Whh1[j*8+i]; }
      float bi1v = bih1[j], bh1 = bhh1[j];
      float h1 = 0.f;
      for (int c=0;c<17;c++){
        if (c >= 1){
          #pragma unroll
          for (int s8=0;s8<8;s8++){
            int t = (c-1)*8 + s8;
            const float* hp0 = h0c[(t>>3)&1][t&7];   // sealed by prior barrier
            float4 a0 = *(const float4*)&hp0[0];
            float4 a1 = *(const float4*)&hp0[4];
            float i0 = wi[0]*a0.x + wi[1]*a0.y + wi[2]*a0.z + wi[3]*a0.w;
            float i1 = wi[4]*a1.x + wi[5]*a1.y + wi[6]*a1.z + wi[7]*a1.w;
            float p0=0.f, p1=0.f;
            #pragma unroll
            for (int i=0;i<4;i++) p0 += wh[i]*__shfl_sync(FULLM, h1, i);
            #pragma unroll
            for (int i=4;i<8;i++) p1 += wh[i]*__shfl_sync(FULLM, h1, i);
            float si1 = bi1v + i0 + i1;
            float s1v = bh1  + p0 + p1;
            float ir  = __shfl_sync(FULLM, si1, jr);
            float izf = __shfl_sync(FULLM, si1, 8+jr);
            float inf = __shfl_sync(FULLM, si1, 16+jr);
            float r1s = __shfl_sync(FULLM, s1v, jr);
            float z1s = __shfl_sync(FULLM, s1v, 8+jr);
            float n1s = __shfl_sync(FULLM, s1v, 16+jr);
            float r1 = sigm(ir + r1s);
            float z1 = sigm(izf + z1s);
            float n1 = tanh_f(inf + r1*n1s);
            h1 = (1.f - z1)*n1 + z1*h1;
            if (lane < 8) hist[t*8+lane] = h1;
          }
        }
        BARRIER_64();
      }
    }
    // softmax post-pass (both warps; hist visible via final bar.sync)
    for (int t = tid; t < 128; t += 64){
      float v[8], m = -1e30f;
      #pragma unroll
      for (int k=0;k<8;k++){ v[k] = hist[t*8+k]; m = fmaxf(m, v[k]); }
      float ssum = 0.f;
      #pragma unroll
      for (int k=0;k<8;k++){ v[k] = __expf(v[k]-m); ssum += v[k]; }
      float inv = __fdividef(1.f, ssum);
      #pragma unroll
      for (int k=0;k<8;k++) outp[t*8+k] = v[k]*inv;
    }
    return;
  }

  // ---------------- ae GEMM path ----------------
  float* xs  = sm;            // 64*128
  float* w1s = sm + 64*128;   // 8*128*16
  int gr0 = (blk - 128) * 64;            // global row 0..16383
  const float* __restrict__ src = (gr0 >= 8192) ? Remote : Local;
  int r0 = gr0 & 8191;
  {
    const float4* w1v = (const float4*)w1;
    float4* w1sv = (float4*)w1s;
    for (int k = tid; k < 4096; k += 256) w1sv[k] = w1v[k];
    float4* xsv = (float4*)xs;
    for (int k = tid; k < 64*32; k += 256){
      int rr = k >> 5, f4 = k & 31;
      const float4* rp = (const float4*)(src + (size_t)(r0+rr)*132);
      xsv[rr*32 + f4] = rp[f4];
    }
  }
  __syncthreads();
  int jj = tid & 15, rb = tid >> 4;
  float acc[4][8];
  #pragma unroll
  for (int q=0;q<4;q++)
    #pragma unroll
    for (int e=0;e<8;e++) acc[q][e]=0.f;
  for (int i=0;i<128;i++){
    float x0 = xs[(rb     )*128 + i];
    float x1 = xs[(rb + 16)*128 + i];
    float x2 = xs[(rb + 32)*128 + i];
    float x3 = xs[(rb + 48)*128 + i];
    #pragma unroll
    for (int e=0;e<8;e++){
      float wv = w1s[(e*128 + i)*16 + jj];
      acc[0][e] += wv*x0; acc[1][e] += wv*x1; acc[2][e] += wv*x2; acc[3][e] += wv*x3;
    }
  }
  #pragma unroll
  for (int q=0;q<4;q++){
    int grow = gr0 + rb + q*16;
    float* outp = g_he + (size_t)grow*128;
    #pragma unroll
    for (int e=0;e<8;e++) outp[e*16+jj] = acc[q][e] + b1[e*16+jj];
  }
}

// -- mix: h = sum_e om_e * he_e, plus deterministic per-block bn partials ----
__global__ __launch_bounds__(256) void mix_kernel()
{
  __shared__ float red1[256], red2[256];
  int blk = blockIdx.x;               // 128 blocks, 128 consecutive rows each
  int tid = threadIdx.x;
  int jj  = tid & 15;                 // constant per thread (256 % 16 == 0)
  float s1 = 0.f, s2 = 0.f;
  for (int it = tid; it < 128*16; it += 256){
    int rl = it >> 4;
    int grow = blk*128 + rl;
    const float* he = g_he + (size_t)grow*128;
    const float* om = ((grow < 8192) ? g_Lo : g_Ro) + (size_t)(grow & 8191)*8;
    float s = 0.f;
    #pragma unroll
    for (int e=0;e<8;e++) s += om[e]*he[e*16+jj];
    ((grow < 8192) ? g_hL : g_hR)[(grow & 8191)*16 + jj] = s;
    s1 += s; s2 += s*s;
  }
  red1[tid] = s1; red2[tid] = s2;
  __syncthreads();
  if (tid < 16){
    float a = 0.f, b = 0.f;
    #pragma unroll
    for (int k=0;k<16;k++){ a += red1[tid + 16*k]; b += red2[tid + 16*k]; }
    g_part[(blk*16+tid)*2+0] = a;
    g_part[(blk*16+tid)*2+1] = b;
  }
}

// -- Z = mix(elu(bn(hL)))@w2 + mix(elu(bn(hR)))@w2, then xW for mid layer0 --
// bn stats reconstructed from g_part (blocks 0..63 = Local, 64..127 = Remote)
__global__ __launch_bounds__(256) void z_kernel(
    const float* __restrict__ w2, const float* __restrict__ b2,
    const float* __restrict__ gam, const float* __restrict__ bet,
    const float* __restrict__ mWih0, const float* __restrict__ mbih0)
{
  __shared__ float w2s[2048];
  __shared__ float hnL[256], hnR[256], omLs[128], omRs[128], zs[256];
  int tid = threadIdx.x;
  int row0 = blockIdx.x * 16;
  for (int k=tid;k<2048;k+=256) w2s[k]=w2[k];
  for (int k=tid;k<128;k+=256){ omLs[k]=g_Lo[row0*8+k]; omRs[k]=g_Ro[row0*8+k]; }
  int r = tid>>4, jj = tid&15;
  {
    float S1L=0.f,S2L=0.f,S1R=0.f,S2R=0.f;
    for (int bb=0; bb<64; bb++){
      S1L += g_part[((bb   )*16+jj)*2+0];  S2L += g_part[((bb   )*16+jj)*2+1];
      S1R += g_part[((64+bb)*16+jj)*2+0];  S2R += g_part[((64+bb)*16+jj)*2+1];
    }
    float mL = S1L*(1.f/8192.f);
    float sL = rsqrtf(S2L*(1.f/8192.f) - mL*mL + 1e-5f);
    float mR = S1R*(1.f/8192.f);
    float sR = rsqrtf(S2R*(1.f/8192.f) - mR*mR + 1e-5f);
    float gg = gam[jj], bb2 = bet[jj];
    float u = gg*(g_hL[(row0+r)*16+jj]-mL)*sL + bb2;
    hnL[tid] = u>0.f ? u : (__expf(u)-1.f);
    u = gg*(g_hR[(row0+r)*16+jj]-mR)*sR + bb2;
    hnR[tid] = u>0.f ? u : (__expf(u)-1.f);
  }
  __syncthreads();
  float zacc = 0.f;
  #pragma unroll
  for (int e=0;e<8;e++){
    float bb = b2[e*16+jj];
    float sL = bb, sR = bb;
    #pragma unroll
    for (int q=0;q<16;q++){
      float wv = w2s[e*256 + q*16 + jj];
      sL += hnL[r*16+q]*wv;
      sR += hnR[r*16+q]*wv;
    }
    zacc += omLs[r*8+e]*sL + omRs[r*8+e]*sR;
  }
  zs[tid] = zacc;
  __syncthreads();
  for (int k=tid;k<16*48;k+=256){
    int rr = k/48, g48 = k - rr*48;
    float s = mbih0[g48];
    #pragma unroll
    for (int i=0;i<16;i++) s += zs[rr*16+i]*mWih0[g48*16+i];
    g_mxw[(size_t)(row0+rr)*48 + g48] = s;
  }
}

// ---------------- mid GRU: 2 layers, hidden 16, 128 steps -------------------
// 2 warps/block: warp 0 = layer0 producer, warp 1 = layer1 consumer one
// 8-step chunk behind; h0 handoff via double-buffered smem chunk ring.
// Intra-warp h broadcast via shfl (no per-step syncwarp / smem readback).
__global__ __launch_bounds__(64) void mid_kernel(
    const float* __restrict__ Whh0, const float* __restrict__ bhh0,
    const float* __restrict__ Wih1, const float* __restrict__ bih1,
    const float* __restrict__ Whh1, const float* __restrict__ bhh1)
{
  __shared__ float xw[128*48];
  __shared__ __align__(16) float h0c[2][8][16];
  int b = blockIdx.x, tid = threadIdx.x;
  int warp = tid >> 5, lane = tid & 31;
  int jr = lane & 15;
  {
    const float4* src4 = (const float4*)(g_mxw + (size_t)b*6144);
    float4* dst4 = (float4*)xw;
    for (int k=tid;k<1536;k+=64) dst4[k]=src4[k];
  }
  int la = lane, lb = 32 + jr;

  if (warp == 0){
    // -------- producer: layer0 --------
    float wa[16], wb[16];
    #pragma unroll
    for (int i=0;i<16;i++){ wa[i]=Whh0[la*16+i]; wb[i]=Whh0[lb*16+i]; }
    float ba=bhh0[la], bb2=bhh0[lb];
    __syncthreads();
    float h0 = 0.f;
    for (int c=0;c<17;c++){
      if (c<16){
        #pragma unroll
        for (int s8=0;s8<8;s8++){
          int t = c*8 + s8;
          float sa, sb;
          if (t == 0){ sa = ba; sb = bb2; }
          else {
            float sa0=0.f,sa1=0.f,sb0=0.f,sb1=0.f;
            #pragma unroll
            for (int i=0;i<8;i++){ float hvv=__shfl_sync(FULLM,h0,i); sa0+=wa[i]*hvv; sb0+=wb[i]*hvv; }
            #pragma unroll
            for (int i=8;i<16;i++){ float hvv=__shfl_sync(FULLM,h0,i); sa1+=wa[i]*hvv; sb1+=wb[i]*hvv; }
            sa = ba + sa0 + sa1;
            sb = bb2 + sb0 + sb1;
          }
          const float* xwt = xw + t*48;
          float saz = __shfl_sync(FULLM, sa, 16+jr);
          float r = sigm(xwt[jr] + sa);
          float z = sigm(xwt[16+jr] + saz);
          float n = tanh_f(xwt[32+jr] + r*sb);
          h0 = (1.f - z)*n + z*h0;
          if (lane < 16) h0c[(t>>3)&1][t&7][jr] = h0;
        }
      }
      BARRIER_64();
    }
  } else {
    // -------- consumer: layer1 --------
    float wia[16], wib[16], wha[16], whb[16];
    #pragma unroll
    for (int i=0;i<16;i++){ wia[i]=Wih1[la*16+i]; wib[i]=Wih1[lb*16+i];
                            wha[i]=Whh1[la*16+i]; whb[i]=Whh1[lb*16+i]; }
    float bia=bih1[la], bib=bih1[lb], bha=bhh1[la], bhb=bhh1[lb];
    __syncthreads();
    float h1 = 0.f;
    for (int c=0;c<17;c++){
      if (c >= 1){
        #pragma unroll
        for (int s8=0;s8<8;s8++){
          int t = (c-1)*8 + s8;
          const float* hp0 = h0c[(t>>3)&1][t&7];   // sealed by prior barrier
          float4 a0=*(const float4*)&hp0[0],  a1=*(const float4*)&hp0[4];
          float4 a2=*(const float4*)&hp0[8],  a3=*(const float4*)&hp0[12];
          float hv[16]={a0.x,a0.y,a0.z,a0.w, a1.x,a1.y,a1.z,a1.w,
                        a2.x,a2.y,a2.z,a2.w, a3.x,a3.y,a3.z,a3.w};
          float ia0=0.f,ia1=0.f,ib0=0.f,ib1=0.f;
          #pragma unroll
          for (int i=0;i<8;i++){ ia0+=wia[i]*hv[i]; ib0+=wib[i]*hv[i]; }
          #pragma unroll
          for (int i=8;i<16;i++){ ia1+=wia[i]*hv[i]; ib1+=wib[i]*hv[i]; }
          float sc0=0.f,sc1=0.f,sd0=0.f,sd1=0.f;
          #pragma unroll
          for (int i=0;i<8;i++){ float hwv=__shfl_sync(FULLM,h1,i); sc0+=wha[i]*hwv; sd0+=whb[i]*hwv; }
          #pragma unroll
          for (int i=8;i<16;i++){ float hwv=__shfl_sync(FULLM,h1,i); sc1+=wha[i]*hwv; sd1+=whb[i]*hwv; }
          float ia  = bia + ia0 + ia1;
          float ib  = bib + ib0 + ib1;
          float s1a = bha + sc0 + sc1;
          float s1b = bhb + sd0 + sd1;
          float iz = __shfl_sync(FULLM, ia,  16+jr);
          float sz = __shfl_sync(FULLM, s1a, 16+jr);
          float r1 = sigm(ia + s1a);
          float z1 = sigm(iz + sz);
          float n1 = tanh_f(ib + r1*s1b);
          h1 = (1.f - z1)*n1 + z1*h1;
        }
      }
      BARRIER_64();
    }
    if (lane < 16) g_zlast[b*16+jr] = h1;
  }
}

// ---------------- decoder stage 1: h, batchnorm(64), elu --------------------
__global__ __launch_bounds__(512) void dec_h_kernel(
    const float* __restrict__ Remote,
    const float* __restrict__ w1, const float* __restrict__ b1,
    const float* __restrict__ gam, const float* __restrict__ bet)
{
  __shared__ float din[64*17];
  __shared__ float ro[64*8];
  __shared__ float hsm[64*16];
  __shared__ float mv[32];
  int tid = threadIdx.x;
  for (int k=tid;k<1024;k+=512) din[(k>>4)*17 + (k&15)] = g_zlast[k];
  if (tid < 64) din[tid*17+16] = Remote[((size_t)tid*128+127)*132 + 131];
  ro[tid & 511] = g_Ro[(((size_t)(tid>>3))*128+127)*8 + (tid&7)];
  __syncthreads();
  for (int k=tid;k<1024;k+=512){
    int b=k>>4, jj=k&15;
    float acc=0.f;
    #pragma unroll
    for (int e=0;e<8;e++){
      float s = b1[e*16+jj];
      #pragma unroll
      for (int i=0;i<17;i++) s += din[b*17+i]*w1[e*272 + i*16 + jj];
      acc += ro[b*8+e]*s;
    }
    hsm[k]=acc;
  }
  __syncthreads();
  if (tid<16){
    float s1=0.f,s2=0.f;
    for (int b=0;b<64;b++){ float v=hsm[b*16+tid]; s1+=v; s2+=v*v; }
    float m=s1*(1.f/64.f), var=s2*(1.f/64.f)-m*m;
    mv[tid]=m; mv[16+tid]=rsqrtf(var+1e-5f);
  }
  __syncthreads();
  for (int k=tid;k<1024;k+=512){
    int jj=k&15;
    float u = gam[jj]*(hsm[k]-mv[jj])*mv[16+jj] + bet[jj];
    g_hdec[k] = u>0.f ? u : (__expf(u)-1.f);
  }
}

// ---------------- decoder stage 2: out = mix(hn @ w2 + b2) ------------------
__global__ __launch_bounds__(256) void dec_out_kernel(
    const float* __restrict__ w2, const float* __restrict__ b2,
    float* __restrict__ out)
{
  int k = blockIdx.x*256 + threadIdx.x;
  int b = k >> 7, o = k & 127;
  float ro[8], hn[16];
  #pragma unroll
  for (int e=0;e<8;e++) ro[e]=g_Ro[((size_t)b*128+127)*8+e];
  #pragma unroll
  for (int jj=0;jj<16;jj++) hn[jj]=g_hdec[b*16+jj];
  float acc=0.f;
  #pragma unroll
  for (int e=0;e<8;e++){
    float s=b2[e*128+o];
    #pragma unroll
    for (int jj=0;jj<16;jj++) s += hn[jj]*w2[e*2048 + jj*128 + o];
    acc += ro[e]*s;
  }
  out[k]=acc;
}

// ---------------------------------------------------------------------------
extern "C" void kernel_launch(void* const* d_in, const int* in_sizes, int n_in,
                              void* d_out, int out_size)
{
  (void)out_size;
  const float *Local=(const float*)d_in[0], *Remote=(const float*)d_in[1];
  // resolve remaining params by element count (robust to metadata ordering)
  const float *gWih0=nullptr, *aeW2=nullptr, *mdW1=nullptr, *mdB2=nullptr;
  const float *a192[3]={0,0,0}, *a24[4]={0,0,0,0}, *a768[4]={0,0,0,0},
              *a48[4]={0,0,0,0}, *a16384[2]={0,0}, *a128[3]={0,0,0}, *a16[4]={0,0,0,0};
  int c192=0,c24=0,c768=0,c48=0,c16384=0,c128=0,c16=0;
  for (int i=2;i<n_in;i++){
    const float* p=(const float*)d_in[i];
    switch(in_sizes[i]){
      case 72:    gWih0=p; break;
      case 192:   if(c192<3)   a192[c192++]=p; break;
      case 24:    if(c24<4)    a24[c24++]=p; break;
      case 768:   if(c768<4)   a768[c768++]=p; break;
      case 48:    if(c48<4)    a48[c48++]=p; break;
      case 16384: if(c16384<2) a16384[c16384++]=p; break;
      case 128:   if(c128<3)   a128[c128++]=p; break;
      case 2048:  aeW2=p; break;
      case 2176:  mdW1=p; break;
      case 1024:  mdB2=p; break;
      case 16:    if(c16<4)    a16[c16++]=p; break;
      default: break;
    }
  }
  const float *gWhh0=a192[0], *gWih1=a192[1], *gWhh1=a192[2];
  const float *gbih0=a24[0], *gbhh0=a24[1], *gbih1=a24[2], *gbhh1=a24[3];
  const float *mWih0=a768[0], *mWhh0=a768[1], *mWih1=a768[2], *mWhh1=a768[3];
  const float *mbih0=a48[0], *mbhh0=a48[1], *mbih1=a48[2], *mbhh1=a48[3];
  const float *aeW1=a16384[0], *mdW2=a16384[1];
  const float *aeB1=a128[0], *aeB2=a128[1], *mdB1=a128[2];
  const float *aeG=a16[0], *aeBT=a16[1], *mdG=a16[2], *mdBT=a16[3];

  cudaFuncSetAttribute(fat_kernel, cudaFuncAttributeMaxDynamicSharedMemorySize, 98304);

  fat_kernel<<<384,256,98304>>>(Local,Remote,
      gWih0,gWhh0,gbih0,gbhh0,gWih1,gWhh1,gbih1,gbhh1, aeW1,aeB1);
  mix_kernel<<<128,256>>>();
  z_kernel<<<512,256>>>(aeW2,aeB2,aeG,aeBT,mWih0,mbih0);
  mid_kernel<<<64,64>>>(mWhh0,mbhh0,mWih1,mbih1,mWhh1,mbhh1);
  dec_h_kernel<<<1,512>>>(Remote,mdW1,mdB1,mdG,mdBT);
  dec_out_kernel<<<32,256>>>(mdW2,mdB2,(float*)d_out);
}

// round 13
// speedup vs baseline: 1.2230x; 1.2230x over previous
#include <cuda_runtime.h>

#define FULLM 0xFFFFFFFFu

// ---------------- scratch (device globals; no allocations allowed) ----------
static __device__ float g_Lo[64*128*8];
static __device__ float g_Ro[64*128*8];
static __device__ float g_he[16384*128];  // unmixed per-expert h: [grow][e*16+j]
static __device__ float g_hL[8192*16];
static __device__ float g_hR[8192*16];
static __device__ float g_part[128*16*2]; // per-mix-block {sum,sumsq} per column
static __device__ float g_mxw[8192*48];   // xW for mid-GRU layer0 (incl. bias)
static __device__ float g_zlast[64*16];
static __device__ float g_hdec[64*16];

// fast activations (scan kernels only; MUFU.TANH, max abs err ~5e-4)
__device__ __forceinline__ float tanh_f(float x){
  float y;
  asm("tanh.approx.f32 %0, %1;" : "=f"(y) : "f"(x));
  return y;
}
__device__ __forceinline__ float sigm(float x){
  return 0.5f*tanh_f(0.5f*x) + 0.5f;
}
#define BARRIER_64() asm volatile("bar.sync 1, 64;" ::: "memory")

// ---------------- fat kernel: gate GRU (blocks 0..127) + ae GEMM (128..383) --
// gate: warp 0 = GRU layer0, warp 1 = GRU layer1 one 8-step chunk behind;
//       h0 handed off via double-buffered smem chunk ring + bar.sync.
// gemm: 64 rows/block, w1 (64KB) + x (32KB) staged in dynamic smem; writes
//       UNMIXED per-expert h (+b1) to g_he — no dependency on gate output.
__global__ __launch_bounds__(256) void fat_kernel(
    const float* __restrict__ Local, const float* __restrict__ Remote,
    const float* __restrict__ Wih0, const float* __restrict__ Whh0,
    const float* __restrict__ bih0, const float* __restrict__ bhh0,
    const float* __restrict__ Wih1, const float* __restrict__ Whh1,
    const float* __restrict__ bih1, const float* __restrict__ bhh1,
    const float* __restrict__ w1, const float* __restrict__ b1)
{
  extern __shared__ float sm[];
  int blk = blockIdx.x;
  int tid = threadIdx.x;

  if (blk < 128){
    // ---------------- gate GRU path ----------------
    float* xw0  = sm;                                  // 128*24
    float* hist = sm + 3072;                           // 128*8
    float (*h0c)[8][8] = (float(*)[8][8])(sm + 4096);  // chunk ring (16B-aligned)
    float (*h1b)[8]    = (float(*)[8])(sm + 4224);     // h1 self double-buffer
    const float* __restrict__ seq = ((blk < 64) ? Local : Remote) + (size_t)(blk & 63)*(128*132);
    float* outp = ((blk < 64) ? g_Lo : g_Ro) + (size_t)(blk & 63)*(128*8);

    // all 256 threads precompute xW for layer0 (features at [...,128..130])
    for (int idx = tid; idx < 128*24; idx += 256){
      int t = idx / 24, j = idx - t*24;
      const float* xp = seq + t*132 + 128;
      xw0[idx] = bih0[j] + Wih0[j*3+0]*xp[0] + Wih0[j*3+1]*xp[1] + Wih0[j*3+2]*xp[2];
    }
    __syncthreads();
    if (tid >= 64) return;

    int warp = tid >> 5, lane = tid & 31;
    int j = (lane < 24) ? lane : 0;
    int jr = lane & 7;

    if (warp == 0){
      // -------- producer: layer0 --------
      float w0[8];
      #pragma unroll
      for (int i=0;i<8;i++) w0[i]=Whh0[j*8+i];
      float b0 = bhh0[j];
      float h0 = 0.f;
      for (int c=0;c<17;c++){
        if (c<16){
          #pragma unroll
          for (int s8=0;s8<8;s8++){
            int t = c*8 + s8;
            float s;
            if (t == 0){ s = b0; }
            else {
              __syncwarp();
              const float* hp = h0c[((t-1)>>3)&1][(t-1)&7];
              float4 a0 = *(const float4*)&hp[0];
              float4 a1 = *(const float4*)&hp[4];
              float p0 = w0[0]*a0.x + w0[1]*a0.y + w0[2]*a0.z + w0[3]*a0.w;
              float p1 = w0[4]*a1.x + w0[5]*a1.y + w0[6]*a1.z + w0[7]*a1.w;
              s = b0 + p0 + p1;
            }
            float sr = __shfl_sync(FULLM, s, jr);
            float sz = __shfl_sync(FULLM, s, 8+jr);
            float sn = __shfl_sync(FULLM, s, 16+jr);
            float r = sigm(xw0[t*24 + jr]      + sr);
            float z = sigm(xw0[t*24 + 8 + jr]  + sz);
            float n = tanh_f(xw0[t*24 + 16 + jr] + r*sn);
            h0 = (1.f - z)*n + z*h0;
            if (lane < 8) h0c[(t>>3)&1][t&7][lane] = h0;
          }
        }
        BARRIER_64();
      }
    } else {
      // -------- consumer: layer1 (one chunk behind) --------
      float wi[8], wh[8];
      #pragma unroll
      for (int i=0;i<8;i++){ wi[i]=Wih1[j*8+i]; wh[i]=Whh1[j*8+i]; }
      float bi1v = bih1[j], bh1 = bhh1[j];
      if (lane < 8) h1b[1][lane] = 0.f;
      float h1 = 0.f;
      for (int c=0;c<17;c++){
        if (c >= 1){
          #pragma unroll
          for (int s8=0;s8<8;s8++){
            int t = (c-1)*8 + s8;
            __syncwarp();
            const float* hp0 = h0c[(t>>3)&1][t&7];
            const float* hp1 = h1b[(t+1)&1];
            float4 a0 = *(const float4*)&hp0[0];
            float4 a1 = *(const float4*)&hp0[4];
            float4 b0 = *(const float4*)&hp1[0];
            float4 b1 = *(const float4*)&hp1[4];
            float i0 = wi[0]*a0.x + wi[1]*a0.y + wi[2]*a0.z + wi[3]*a0.w;
            float i1 = wi[4]*a1.x + wi[5]*a1.y + wi[6]*a1.z + wi[7]*a1.w;
            float p0 = wh[0]*b0.x + wh[1]*b0.y + wh[2]*b0.z + wh[3]*b0.w;
            float p1 = wh[4]*b1.x + wh[5]*b1.y + wh[6]*b1.z + wh[7]*b1.w;
            float si1 = bi1v + i0 + i1;
            float s1v = bh1  + p0 + p1;
            float ir  = __shfl_sync(FULLM, si1, jr);
            float izf = __shfl_sync(FULLM, si1, 8+jr);
            float inf = __shfl_sync(FULLM, si1, 16+jr);
            float r1s = __shfl_sync(FULLM, s1v, jr);
            float z1s = __shfl_sync(FULLM, s1v, 8+jr);
            float n1s = __shfl_sync(FULLM, s1v, 16+jr);
            float r1 = sigm(ir + r1s);
            float z1 = sigm(izf + z1s);
            float n1 = tanh_f(inf + r1*n1s);
            h1 = (1.f - z1)*n1 + z1*h1;
            if (lane < 8){ hist[t*8+lane] = h1; h1b[t&1][lane] = h1; }
          }
        }
        BARRIER_64();
      }
    }
    // softmax post-pass (both warps; hist visible via final bar.sync)
    for (int t = tid; t < 128; t += 64){
      float v[8], m = -1e30f;
      #pragma unroll
      for (int k=0;k<8;k++){ v[k] = hist[t*8+k]; m = fmaxf(m, v[k]); }
      float ssum = 0.f;
      #pragma unroll
      for (int k=0;k<8;k++){ v[k] = __expf(v[k]-m); ssum += v[k]; }
      float inv = __fdividef(1.f, ssum);
      #pragma unroll
      for (int k=0;k<8;k++) outp[t*8+k] = v[k]*inv;
    }
    return;
  }

  // ---------------- ae GEMM path ----------------
  float* xs  = sm;            // 64*128
  float* w1s = sm + 64*128;   // 8*128*16
  int gr0 = (blk - 128) * 64;            // global row 0..16383
  const float* __restrict__ src = (gr0 >= 8192) ? Remote : Local;
  int r0 = gr0 & 8191;
  {
    const float4* w1v = (const float4*)w1;
    float4* w1sv = (float4*)w1s;
    for (int k = tid; k < 4096; k += 256) w1sv[k] = w1v[k];
    float4* xsv = (float4*)xs;
    for (int k = tid; k < 64*32; k += 256){
      int rr = k >> 5, f4 = k & 31;
      const float4* rp = (const float4*)(src + (size_t)(r0+rr)*132);
      xsv[rr*32 + f4] = rp[f4];
    }
  }
  __syncthreads();
  int jj = tid & 15, rb = tid >> 4;
  float acc[4][8];
  #pragma unroll
  for (int q=0;q<4;q++)
    #pragma unroll
    for (int e=0;e<8;e++) acc[q][e]=0.f;
  for (int i=0;i<128;i++){
    float x0 = xs[(rb     )*128 + i];
    float x1 = xs[(rb + 16)*128 + i];
    float x2 = xs[(rb + 32)*128 + i];
    float x3 = xs[(rb + 48)*128 + i];
    #pragma unroll
    for (int e=0;e<8;e++){
      float wv = w1s[(e*128 + i)*16 + jj];
      acc[0][e] += wv*x0; acc[1][e] += wv*x1; acc[2][e] += wv*x2; acc[3][e] += wv*x3;
    }
  }
  #pragma unroll
  for (int q=0;q<4;q++){
    int grow = gr0 + rb + q*16;
    float* outp = g_he + (size_t)grow*128;
    #pragma unroll
    for (int e=0;e<8;e++) outp[e*16+jj] = acc[q][e] + b1[e*16+jj];
  }
}

// -- mix: h = sum_e om_e * he_e, plus deterministic per-block bn partials ----
__global__ __launch_bounds__(256) void mix_kernel()
{
  __shared__ float red1[256], red2[256];
  int blk = blockIdx.x;               // 128 blocks, 128 consecutive rows each
  int tid = threadIdx.x;
  int jj  = tid & 15;                 // constant per thread (256 % 16 == 0)
  float s1 = 0.f, s2 = 0.f;
  for (int it = tid; it < 128*16; it += 256){
    int rl = it >> 4;
    int grow = blk*128 + rl;
    const float* he = g_he + (size_t)grow*128;
    const float* om = ((grow < 8192) ? g_Lo : g_Ro) + (size_t)(grow & 8191)*8;
    float s = 0.f;
    #pragma unroll
    for (int e=0;e<8;e++) s += om[e]*he[e*16+jj];
    ((grow < 8192) ? g_hL : g_hR)[(grow & 8191)*16 + jj] = s;
    s1 += s; s2 += s*s;
  }
  red1[tid] = s1; red2[tid] = s2;
  __syncthreads();
  if (tid < 16){
    float a = 0.f, b = 0.f;
    #pragma unroll
    for (int k=0;k<16;k++){ a += red1[tid + 16*k]; b += red2[tid + 16*k]; }
    g_part[(blk*16+tid)*2+0] = a;
    g_part[(blk*16+tid)*2+1] = b;
  }
}

// -- Z = mix(elu(bn(hL)))@w2 + mix(elu(bn(hR)))@w2, then xW for mid layer0 --
// bn stats computed by 32 threads/block into smem (not by all 256).
__global__ __launch_bounds__(256) void z_kernel(
    const float* __restrict__ w2, const float* __restrict__ b2,
    const float* __restrict__ gam, const float* __restrict__ bet,
    const float* __restrict__ mWih0, const float* __restrict__ mbih0)
{
  __shared__ float w2s[2048];
  __shared__ float hnL[256], hnR[256], omLs[128], omRs[128], zs[256];
  __shared__ float mvs[4][16];   // [mL, sL, mR, sR][jj]
  int tid = threadIdx.x;
  int row0 = blockIdx.x * 16;
  for (int k=tid;k<2048;k+=256) w2s[k]=w2[k];
  for (int k=tid;k<128;k+=256){ omLs[k]=g_Lo[row0*8+k]; omRs[k]=g_Ro[row0*8+k]; }
  if (tid < 32){
    int c = tid & 15;
    int base = (tid < 16) ? 0 : 64;
    float S1=0.f, S2=0.f;
    for (int bb=0; bb<64; bb++){
      S1 += g_part[((base+bb)*16+c)*2+0];
      S2 += g_part[((base+bb)*16+c)*2+1];
    }
    float m = S1*(1.f/8192.f);
    float s = rsqrtf(S2*(1.f/8192.f) - m*m + 1e-5f);
    mvs[(tid<16)?0:2][c] = m;
    mvs[(tid<16)?1:3][c] = s;
  }
  __syncthreads();
  int r = tid>>4, jj = tid&15;
  {
    float gg = gam[jj], bb2 = bet[jj];
    float u = gg*(g_hL[(row0+r)*16+jj]-mvs[0][jj])*mvs[1][jj] + bb2;
    hnL[tid] = u>0.f ? u : (__expf(u)-1.f);
    u = gg*(g_hR[(row0+r)*16+jj]-mvs[2][jj])*mvs[3][jj] + bb2;
    hnR[tid] = u>0.f ? u : (__expf(u)-1.f);
  }
  __syncthreads();
  float zacc = 0.f;
  #pragma unroll
  for (int e=0;e<8;e++){
    float bb = b2[e*16+jj];
    float sL = bb, sR = bb;
    #pragma unroll
    for (int q=0;q<16;q++){
      float wv = w2s[e*256 + q*16 + jj];
      sL += hnL[r*16+q]*wv;
      sR += hnR[r*16+q]*wv;
    }
    zacc += omLs[r*8+e]*sL + omRs[r*8+e]*sR;
  }
  zs[tid] = zacc;
  __syncthreads();
  for (int k=tid;k<16*48;k+=256){
    int rr = k/48, g48 = k - rr*48;
    float s = mbih0[g48];
    #pragma unroll
    for (int i=0;i<16;i++) s += zs[rr*16+i]*mWih0[g48*16+i];
    g_mxw[(size_t)(row0+rr)*48 + g48] = s;
  }
}

// ---------------- mid GRU: 2 layers, hidden 16, 128 steps -------------------
// 2 warps/block: warp 0 = layer0 producer, warp 1 = layer1 consumer one
// 8-step chunk behind; h0 handoff via double-buffered smem chunk ring.
__global__ __launch_bounds__(64) void mid_kernel(
    const float* __restrict__ Whh0, const float* __restrict__ bhh0,
    const float* __restrict__ Wih1, const float* __restrict__ bih1,
    const float* __restrict__ Whh1, const float* __restrict__ bhh1)
{
  __shared__ float xw[128*48];
  __shared__ __align__(16) float h0c[2][8][16];
  __shared__ __align__(16) float h1buf[2][16];
  int b = blockIdx.x, tid = threadIdx.x;
  int warp = tid >> 5, lane = tid & 31;
  int jr = lane & 15;
  {
    const float4* src4 = (const float4*)(g_mxw + (size_t)b*6144);
    float4* dst4 = (float4*)xw;
    for (int k=tid;k<1536;k+=64) dst4[k]=src4[k];
  }
  int la = lane, lb = 32 + jr;

  if (warp == 0){
    // -------- producer: layer0 --------
    float wa[16], wb[16];
    #pragma unroll
    for (int i=0;i<16;i++){ wa[i]=Whh0[la*16+i]; wb[i]=Whh0[lb*16+i]; }
    float ba=bhh0[la], bb2=bhh0[lb];
    __syncthreads();
    float h0 = 0.f;
    for (int c=0;c<17;c++){
      if (c<16){
        #pragma unroll
        for (int s8=0;s8<8;s8++){
          int t = c*8 + s8;
          float sa, sb;
          if (t == 0){ sa = ba; sb = bb2; }
          else {
            __syncwarp();
            const float* hp = h0c[((t-1)>>3)&1][(t-1)&7];
            float4 a0=*(const float4*)&hp[0],  a1=*(const float4*)&hp[4];
            float4 a2=*(const float4*)&hp[8],  a3=*(const float4*)&hp[12];
            float hv[16]={a0.x,a0.y,a0.z,a0.w, a1.x,a1.y,a1.z,a1.w,
                          a2.x,a2.y,a2.z,a2.w, a3.x,a3.y,a3.z,a3.w};
            float sa0=0.f,sa1=0.f,sb0=0.f,sb1=0.f;
            #pragma unroll
            for (int i=0;i<8;i++){ sa0+=wa[i]*hv[i]; sb0+=wb[i]*hv[i]; }
            #pragma unroll
            for (int i=8;i<16;i++){ sa1+=wa[i]*hv[i]; sb1+=wb[i]*hv[i]; }
            sa = ba + sa0 + sa1;
            sb = bb2 + sb0 + sb1;
          }
          const float* xwt = xw + t*48;
          float saz = __shfl_sync(FULLM, sa, 16+jr);
          float r = sigm(xwt[jr] + sa);
          float z = sigm(xwt[16+jr] + saz);
          float n = tanh_f(xwt[32+jr] + r*sb);
          h0 = (1.f - z)*n + z*h0;
          if (lane < 16) h0c[(t>>3)&1][t&7][jr] = h0;
        }
      }
      BARRIER_64();
    }
  } else {
    // -------- consumer: layer1 --------
    float wia[16], wib[16], wha[16], whb[16];
    #pragma unroll
    for (int i=0;i<16;i++){ wia[i]=Wih1[la*16+i]; wib[i]=Wih1[lb*16+i];
                            wha[i]=Whh1[la*16+i]; whb[i]=Whh1[lb*16+i]; }
    float bia=bih1[la], bib=bih1[lb], bha=bhh1[la], bhb=bhh1[lb];
    if (lane < 16) h1buf[1][jr] = 0.f;
    __syncthreads();
    float h1 = 0.f;
    for (int c=0;c<17;c++){
      if (c >= 1){
        #pragma unroll
        for (int s8=0;s8<8;s8++){
          int t = (c-1)*8 + s8;
          __syncwarp();
          const float* hp0 = h0c[(t>>3)&1][t&7];
          const float* hp1 = h1buf[(t+1)&1];
          float4 a0=*(const float4*)&hp0[0],  a1=*(const float4*)&hp0[4];
          float4 a2=*(const float4*)&hp0[8],  a3=*(const float4*)&hp0[12];
          float4 c0=*(const float4*)&hp1[0],  c1=*(const float4*)&hp1[4];
          float4 c2=*(const float4*)&hp1[8],  c3=*(const float4*)&hp1[12];
          float hv[16]={a0.x,a0.y,a0.z,a0.w, a1.x,a1.y,a1.z,a1.w,
                        a2.x,a2.y,a2.z,a2.w, a3.x,a3.y,a3.z,a3.w};
          float hw[16]={c0.x,c0.y,c0.z,c0.w, c1.x,c1.y,c1.z,c1.w,
                        c2.x,c2.y,c2.z,c2.w, c3.x,c3.y,c3.z,c3.w};
          float ia0=0.f,ia1=0.f,ib0=0.f,ib1=0.f,sc0=0.f,sc1=0.f,sd0=0.f,sd1=0.f;
          #pragma unroll
          for (int i=0;i<8;i++){ ia0+=wia[i]*hv[i]; ib0+=wib[i]*hv[i]; sc0+=wha[i]*hw[i]; sd0+=whb[i]*hw[i]; }
          #pragma unroll
          for (int i=8;i<16;i++){ ia1+=wia[i]*hv[i]; ib1+=wib[i]*hv[i]; sc1+=wha[i]*hw[i]; sd1+=whb[i]*hw[i]; }
          float ia  = bia + ia0 + ia1;
          float ib  = bib + ib0 + ib1;
          float s1a = bha + sc0 + sc1;
          float s1b = bhb + sd0 + sd1;
          float iz = __shfl_sync(FULLM, ia,  16+jr);
          float sz = __shfl_sync(FULLM, s1a, 16+jr);
          float r1 = sigm(ia + s1a);
          float z1 = sigm(iz + sz);
          float n1 = tanh_f(ib + r1*s1b);
          h1 = (1.f - z1)*n1 + z1*h1;
          if (lane < 16) h1buf[t&1][jr] = h1;
        }
      }
      BARRIER_64();
    }
    if (lane < 16) g_zlast[b*16+jr] = h1;
  }
}

// ---------------- decoder stage 1: h, batchnorm(64), elu --------------------
__global__ __launch_bounds__(512) void dec_h_kernel(
    const float* __restrict__ Remote,
    const float* __restrict__ w1, const float* __restrict__ b1,
    const float* __restrict__ gam, const float* __restrict__ bet)
{
  __shared__ float din[64*17];
  __shared__ float ro[64*8];
  __shared__ float hsm[64*16];
  __shared__ float mv[32];
  int tid = threadIdx.x;
  for (int k=tid;k<1024;k+=512) din[(k>>4)*17 + (k&15)] = g_zlast[k];
  if (tid < 64) din[tid*17+16] = Remote[((size_t)tid*128+127)*132 + 131];
  ro[tid & 511] = g_Ro[(((size_t)(tid>>3))*128+127)*8 + (tid&7)];
  __syncthreads();
  for (int k=tid;k<1024;k+=512){
    int b=k>>4, jj=k&15;
    float acc=0.f;
    #pragma unroll
    for (int e=0;e<8;e++){
      float s = b1[e*16+jj];
      #pragma unroll
      for (int i=0;i<17;i++) s += din[b*17+i]*w1[e*272 + i*16 + jj];
      acc += ro[b*8+e]*s;
    }
    hsm[k]=acc;
  }
  __syncthreads();
  if (tid<16){
    float s1=0.f,s2=0.f;
    for (int b=0;b<64;b++){ float v=hsm[b*16+tid]; s1+=v; s2+=v*v; }
    float m=s1*(1.f/64.f), var=s2*(1.f/64.f)-m*m;
    mv[tid]=m; mv[16+tid]=rsqrtf(var+1e-5f);
  }
  __syncthreads();
  for (int k=tid;k<1024;k+=512){
    int jj=k&15;
    float u = gam[jj]*(hsm[k]-mv[jj])*mv[16+jj] + bet[jj];
    g_hdec[k] = u>0.f ? u : (__expf(u)-1.f);
  }
}

// ---------------- decoder stage 2: out = mix(hn @ w2 + b2) ------------------
__global__ __launch_bounds__(256) void dec_out_kernel(
    const float* __restrict__ w2, const float* __restrict__ b2,
    float* __restrict__ out)
{
  int k = blockIdx.x*256 + threadIdx.x;
  int b = k >> 7, o = k & 127;
  float ro[8], hn[16];
  #pragma unroll
  for (int e=0;e<8;e++) ro[e]=g_Ro[((size_t)b*128+127)*8+e];
  #pragma unroll
  for (int jj=0;jj<16;jj++) hn[jj]=g_hdec[b*16+jj];
  float acc=0.f;
  #pragma unroll
  for (int e=0;e<8;e++){
    float s=b2[e*128+o];
    #pragma unroll
    for (int jj=0;jj<16;jj++) s += hn[jj]*w2[e*2048 + jj*128 + o];
    acc += ro[e]*s;
  }
  out[k]=acc;
}

// ---------------------------------------------------------------------------
extern "C" void kernel_launch(void* const* d_in, const int* in_sizes, int n_in,
                              void* d_out, int out_size)
{
  (void)out_size;
  const float *Local=(const float*)d_in[0], *Remote=(const float*)d_in[1];
  // resolve remaining params by element count (robust to metadata ordering)
  const float *gWih0=nullptr, *aeW2=nullptr, *mdW1=nullptr, *mdB2=nullptr;
  const float *a192[3]={0,0,0}, *a24[4]={0,0,0,0}, *a768[4]={0,0,0,0},
              *a48[4]={0,0,0,0}, *a16384[2]={0,0}, *a128[3]={0,0,0}, *a16[4]={0,0,0,0};
  int c192=0,c24=0,c768=0,c48=0,c16384=0,c128=0,c16=0;
  for (int i=2;i<n_in;i++){
    const float* p=(const float*)d_in[i];
    switch(in_sizes[i]){
      case 72:    gWih0=p; break;
      case 192:   if(c192<3)   a192[c192++]=p; break;
      case 24:    if(c24<4)    a24[c24++]=p; break;
      case 768:   if(c768<4)   a768[c768++]=p; break;
      case 48:    if(c48<4)    a48[c48++]=p; break;
      case 16384: if(c16384<2) a16384[c16384++]=p; break;
      case 128:   if(c128<3)   a128[c128++]=p; break;
      case 2048:  aeW2=p; break;
      case 2176:  mdW1=p; break;
      case 1024:  mdB2=p; break;
      case 16:    if(c16<4)    a16[c16++]=p; break;
      default: break;
    }
  }
  const float *gWhh0=a192[0], *gWih1=a192[1], *gWhh1=a192[2];
  const float *gbih0=a24[0], *gbhh0=a24[1], *gbih1=a24[2], *gbhh1=a24[3];
  const float *mWih0=a768[0], *mWhh0=a768[1], *mWih1=a768[2], *mWhh1=a768[3];
  const float *mbih0=a48[0], *mbhh0=a48[1], *mbih1=a48[2], *mbhh1=a48[3];
  const float *aeW1=a16384[0], *mdW2=a16384[1];
  const float *aeB1=a128[0], *aeB2=a128[1], *mdB1=a128[2];
  const float *aeG=a16[0], *aeBT=a16[1], *mdG=a16[2], *mdBT=a16[3];

  cudaFuncSetAttribute(fat_kernel, cudaFuncAttributeMaxDynamicSharedMemorySize, 98304);

  fat_kernel<<<384,256,98304>>>(Local,Remote,
      gWih0,gWhh0,gbih0,gbhh0,gWih1,gWhh1,gbih1,gbhh1, aeW1,aeB1);
  mix_kernel<<<128,256>>>();
  z_kernel<<<512,256>>>(aeW2,aeB2,aeG,aeBT,mWih0,mbih0);
  mid_kernel<<<64,64>>>(mWhh0,mbhh0,mWih1,mbih1,mWhh1,mbhh1);
  dec_h_kernel<<<1,512>>>(Remote,mdW1,mdB1,mdG,mdBT);
  dec_out_kernel<<<32,256>>>(mdW2,mdB2,(float*)d_out);
}